// round 1
// baseline (speedup 1.0000x reference)
#include <cuda_runtime.h>
#include <cuda_bf16.h>

// Problem shape (fixed by the reference)
#define BATCH 4
#define SEQ   4096
#define DIM   1024
#define KD    128
#define MTOT  (BATCH*SEQ)          // 16384

// Scratch for Q,K,V projections: 3 * 16384 * 128 * 4B = 25.2 MB
__device__ float g_qkv[3][(size_t)MTOT * KD];

// ----------------------------------------------------------------------------
// Kernel 1: QKV projection.  Out[m][n] = sum_d X[m][d] * W[d][n]
// M=16384, N=128, K=1024.  Block computes a 128x128 tile with 256 threads,
// each thread an 8x8 micro-tile.  X tile staged transposed in smem.
// grid = (128, 3)  (blockIdx.y selects which weight / output)
// ----------------------------------------------------------------------------
__global__ void __launch_bounds__(256) proj_kernel(
    const float* __restrict__ X,
    const float* __restrict__ Wq,
    const float* __restrict__ Wk,
    const float* __restrict__ Wv)
{
    __shared__ float Xs[32][132];   // Xs[d][m]   (transposed, padded)
    __shared__ float Ws[32][128];   // Ws[d][n]

    const float* W = (blockIdx.y == 0) ? Wq : ((blockIdx.y == 1) ? Wk : Wv);
    float* Out = g_qkv[blockIdx.y];

    const int tid = threadIdx.x;
    const int ty  = tid >> 4;       // 0..15  -> query rows ty*8..ty*8+7
    const int tx  = tid & 15;       // 0..15  -> cols      tx*8..tx*8+7
    const int m0  = blockIdx.x * 128;

    float acc[8][8];
    #pragma unroll
    for (int i = 0; i < 8; i++)
        #pragma unroll
        for (int j = 0; j < 8; j++) acc[i][j] = 0.0f;

    for (int d0 = 0; d0 < DIM; d0 += 32) {
        // --- load X tile [128 rows][32 d] transposed into Xs[d][m] ---
        #pragma unroll
        for (int r = 0; r < 4; r++) {
            int f   = tid + r * 256;        // 1024 float4 total
            int row = f >> 3;               // 8 float4 per 32-float row
            int c4  = f & 7;
            float4 v = *reinterpret_cast<const float4*>(
                &X[(size_t)(m0 + row) * DIM + d0 + c4 * 4]);
            Xs[c4 * 4 + 0][row] = v.x;
            Xs[c4 * 4 + 1][row] = v.y;
            Xs[c4 * 4 + 2][row] = v.z;
            Xs[c4 * 4 + 3][row] = v.w;
        }
        // --- load W chunk (rows d0..d0+31 are contiguous 4096 floats) ---
        {
            const float4* Wsrc = reinterpret_cast<const float4*>(W + (size_t)d0 * KD);
            float4* Wdst = reinterpret_cast<float4*>(&Ws[0][0]);
            #pragma unroll
            for (int r = 0; r < 4; r++) {
                int f = tid + r * 256;
                Wdst[f] = Wsrc[f];
            }
        }
        __syncthreads();

        #pragma unroll 8
        for (int dd = 0; dd < 32; dd++) {
            float a[8], bb[8];
            *reinterpret_cast<float4*>(&a[0]) =
                *reinterpret_cast<const float4*>(&Xs[dd][ty * 8]);
            *reinterpret_cast<float4*>(&a[4]) =
                *reinterpret_cast<const float4*>(&Xs[dd][ty * 8 + 4]);
            *reinterpret_cast<float4*>(&bb[0]) =
                *reinterpret_cast<const float4*>(&Ws[dd][tx * 8]);
            *reinterpret_cast<float4*>(&bb[4]) =
                *reinterpret_cast<const float4*>(&Ws[dd][tx * 8 + 4]);
            #pragma unroll
            for (int i = 0; i < 8; i++)
                #pragma unroll
                for (int j = 0; j < 8; j++)
                    acc[i][j] = fmaf(a[i], bb[j], acc[i][j]);
        }
        __syncthreads();
    }

    #pragma unroll
    for (int i = 0; i < 8; i++) {
        float4* o = reinterpret_cast<float4*>(
            &Out[(size_t)(m0 + ty * 8 + i) * KD + tx * 8]);
        o[0] = make_float4(acc[i][0], acc[i][1], acc[i][2], acc[i][3]);
        o[1] = make_float4(acc[i][4], acc[i][5], acc[i][6], acc[i][7]);
    }
}

// ----------------------------------------------------------------------------
// Kernel 2: flash attention over S=4096 keys, head dim 128.
// One CTA per (batch b, 128-query tile).  256 threads, 8x8 micro-tiles.
// Smem: Qs[128][132] (Q^T, pre-scaled), Kt[128][132] (K^T, reused as P^T),
//       Vs[128][128].  Total 200704 B.
// grid = (32, 4)
// ----------------------------------------------------------------------------
#define QS_OFF 0
#define KT_OFF (128 * 132)
#define VS_OFF (2 * 128 * 132)
#define ATTN_SMEM_BYTES ((2 * 128 * 132 + 128 * 128) * 4)

__global__ void __launch_bounds__(256, 1) attn_kernel(float* __restrict__ Out)
{
    extern __shared__ float smf[];
    float* Qs = smf + QS_OFF;   // [128][132]  Q^T[d][q] * scale
    float* Kt = smf + KT_OFF;   // [128][132]  K^T[d][k], later P^T[k][q]
    float* Vs = smf + VS_OFF;   // [128][128]  V[k][n]

    const float* gq = g_qkv[0];
    const float* gk = g_qkv[1];
    const float* gv = g_qkv[2];

    const int tid = threadIdx.x;
    const int ty  = tid >> 4;
    const int tx  = tid & 15;
    const int b   = blockIdx.y;
    const int q0  = blockIdx.x * 128;
    const float SCALE = 0.08838834764831845f;   // 1/sqrt(128)

    // ---- load Q tile transposed + pre-scaled ----
    {
        const float4* Qp = reinterpret_cast<const float4*>(
            gq + ((size_t)b * SEQ + q0) * KD);
        #pragma unroll
        for (int r = 0; r < 16; r++) {
            int f   = tid + r * 256;    // 4096 float4
            int row = f >> 5;           // 32 float4 per 128-float row
            int c4  = f & 31;
            float4 v = Qp[(size_t)row * 32 + c4];
            Qs[(c4 * 4 + 0) * 132 + row] = v.x * SCALE;
            Qs[(c4 * 4 + 1) * 132 + row] = v.y * SCALE;
            Qs[(c4 * 4 + 2) * 132 + row] = v.z * SCALE;
            Qs[(c4 * 4 + 3) * 132 + row] = v.w * SCALE;
        }
    }

    float m_i[8], l_i[8], acc[8][8];
    #pragma unroll
    for (int i = 0; i < 8; i++) {
        m_i[i] = -1e30f;
        l_i[i] = 0.0f;
        #pragma unroll
        for (int j = 0; j < 8; j++) acc[i][j] = 0.0f;
    }

    for (int t = 0; t < SEQ / 128; t++) {
        const float4* Kp = reinterpret_cast<const float4*>(
            gk + ((size_t)b * SEQ + t * 128) * KD);
        const float4* Vp = reinterpret_cast<const float4*>(
            gv + ((size_t)b * SEQ + t * 128) * KD);

        __syncthreads();    // previous iteration's P^T / V reads complete

        // ---- load K tile transposed, V tile direct ----
        #pragma unroll
        for (int r = 0; r < 16; r++) {
            int f   = tid + r * 256;
            int row = f >> 5;
            int c4  = f & 31;
            float4 v = Kp[(size_t)row * 32 + c4];
            Kt[(c4 * 4 + 0) * 132 + row] = v.x;
            Kt[(c4 * 4 + 1) * 132 + row] = v.y;
            Kt[(c4 * 4 + 2) * 132 + row] = v.z;
            Kt[(c4 * 4 + 3) * 132 + row] = v.w;
            reinterpret_cast<float4*>(Vs)[f] = Vp[f];
        }
        __syncthreads();

        // ---- S = (Q*scale) @ K^T ----
        float s[8][8];
        #pragma unroll
        for (int i = 0; i < 8; i++)
            #pragma unroll
            for (int j = 0; j < 8; j++) s[i][j] = 0.0f;

        #pragma unroll 8
        for (int dd = 0; dd < 128; dd++) {
            float a[8], bb[8];
            *reinterpret_cast<float4*>(&a[0]) =
                *reinterpret_cast<const float4*>(&Qs[dd * 132 + ty * 8]);
            *reinterpret_cast<float4*>(&a[4]) =
                *reinterpret_cast<const float4*>(&Qs[dd * 132 + ty * 8 + 4]);
            *reinterpret_cast<float4*>(&bb[0]) =
                *reinterpret_cast<const float4*>(&Kt[dd * 132 + tx * 8]);
            *reinterpret_cast<float4*>(&bb[4]) =
                *reinterpret_cast<const float4*>(&Kt[dd * 132 + tx * 8 + 4]);
            #pragma unroll
            for (int i = 0; i < 8; i++)
                #pragma unroll
                for (int j = 0; j < 8; j++)
                    s[i][j] = fmaf(a[i], bb[j], s[i][j]);
        }
        __syncthreads();    // everyone done reading Kt before it becomes P^T

        // ---- online softmax update (row reductions across 16 tx lanes) ----
        #pragma unroll
        for (int i = 0; i < 8; i++) {
            float mt = s[i][0];
            #pragma unroll
            for (int j = 1; j < 8; j++) mt = fmaxf(mt, s[i][j]);
            #pragma unroll
            for (int off = 1; off < 16; off <<= 1)
                mt = fmaxf(mt, __shfl_xor_sync(0xffffffffu, mt, off));

            float mnew  = fmaxf(m_i[i], mt);
            float alpha = __expf(m_i[i] - mnew);
            float rsum  = 0.0f;
            #pragma unroll
            for (int j = 0; j < 8; j++) {
                s[i][j] = __expf(s[i][j] - mnew);
                rsum += s[i][j];
            }
            #pragma unroll
            for (int off = 1; off < 16; off <<= 1)
                rsum += __shfl_xor_sync(0xffffffffu, rsum, off);

            l_i[i] = l_i[i] * alpha + rsum;
            m_i[i] = mnew;
            #pragma unroll
            for (int j = 0; j < 8; j++) acc[i][j] *= alpha;
        }

        // ---- write P^T[k][q] into the K buffer ----
        #pragma unroll
        for (int j = 0; j < 8; j++) {
            float4 v0 = make_float4(s[0][j], s[1][j], s[2][j], s[3][j]);
            float4 v1 = make_float4(s[4][j], s[5][j], s[6][j], s[7][j]);
            *reinterpret_cast<float4*>(&Kt[(tx * 8 + j) * 132 + ty * 8])     = v0;
            *reinterpret_cast<float4*>(&Kt[(tx * 8 + j) * 132 + ty * 8 + 4]) = v1;
        }
        __syncthreads();

        // ---- O += P^T' @ V ----
        #pragma unroll 8
        for (int kk = 0; kk < 128; kk++) {
            float a[8], bb[8];
            *reinterpret_cast<float4*>(&a[0]) =
                *reinterpret_cast<const float4*>(&Kt[kk * 132 + ty * 8]);
            *reinterpret_cast<float4*>(&a[4]) =
                *reinterpret_cast<const float4*>(&Kt[kk * 132 + ty * 8 + 4]);
            *reinterpret_cast<float4*>(&bb[0]) =
                *reinterpret_cast<const float4*>(&Vs[kk * 128 + tx * 8]);
            *reinterpret_cast<float4*>(&bb[4]) =
                *reinterpret_cast<const float4*>(&Vs[kk * 128 + tx * 8 + 4]);
            #pragma unroll
            for (int i = 0; i < 8; i++)
                #pragma unroll
                for (int j = 0; j < 8; j++)
                    acc[i][j] = fmaf(a[i], bb[j], acc[i][j]);
        }
    }

    // ---- epilogue: normalize and store ----
    #pragma unroll
    for (int i = 0; i < 8; i++) {
        float inv = 1.0f / l_i[i];
        float4* o = reinterpret_cast<float4*>(
            &Out[((size_t)b * SEQ + q0 + ty * 8 + i) * KD + tx * 8]);
        o[0] = make_float4(acc[i][0] * inv, acc[i][1] * inv,
                           acc[i][2] * inv, acc[i][3] * inv);
        o[1] = make_float4(acc[i][4] * inv, acc[i][5] * inv,
                           acc[i][6] * inv, acc[i][7] * inv);
    }
}

// ----------------------------------------------------------------------------
extern "C" void kernel_launch(void* const* d_in, const int* in_sizes, int n_in,
                              void* d_out, int out_size)
{
    const float* X  = (const float*)d_in[0];
    const float* Wq = (const float*)d_in[1];
    const float* Wk = (const float*)d_in[2];
    const float* Wv = (const float*)d_in[3];
    float* out = (float*)d_out;

    (void)in_sizes; (void)n_in; (void)out_size;

    // idempotent, capture-safe (not a stream op, not an allocation)
    cudaFuncSetAttribute(attn_kernel,
                         cudaFuncAttributeMaxDynamicSharedMemorySize,
                         ATTN_SMEM_BYTES);

    proj_kernel<<<dim3(MTOT / 128, 3), 256>>>(X, Wq, Wk, Wv);
    attn_kernel<<<dim3(SEQ / 128, BATCH), 256, ATTN_SMEM_BYTES>>>(out);
}